// round 15
// baseline (speedup 1.0000x reference)
#include <cuda_runtime.h>

#define T_STEPS 2048
#define BATCH   2048
#define HID     32
#define DF      8
#define DS      24
#define EPAD    34   // ulls per element region (32 rows + 2 pad) = 272 B, keeps 16B align

typedef unsigned long long ull;

__device__ __forceinline__ ull f2_fma(ull a, ull b, ull c) {
    ull d;
    asm("fma.rn.f32x2 %0, %1, %2, %3;" : "=l"(d) : "l"(a), "l"(b), "l"(c));
    return d;
}
__device__ __forceinline__ ull f2_add(ull a, ull b) {
    ull d;
    asm("add.rn.f32x2 %0, %1, %2;" : "=l"(d) : "l"(a), "l"(b));
    return d;
}
__device__ __forceinline__ ull f2_pack(float lo, float hi) {
    ull d;
    asm("mov.b64 %0, {%1, %2};" : "=l"(d) : "f"(lo), "f"(hi));
    return d;
}
__device__ __forceinline__ void f2_unpack(ull v, float &lo, float &hi) {
    asm("mov.b64 {%0, %1}, %2;" : "=f"(lo), "=f"(hi) : "l"(v));
}

// tanh(x) = sign(x) * (1 - e) / (1 + e), e = exp(-2|x|). ~1e-6 abs error.
__device__ __forceinline__ float fast_tanh(float x) {
    float ax = fabsf(x);
    float e  = __expf(-2.0f * ax);
    float r  = __fdividef(1.0f - e, 1.0f + e);
    return __int_as_float((__float_as_int(x) & 0x80000000) | __float_as_int(r));
}

__global__ __launch_bounds__(32)
void chive_kernel(const float* __restrict__ frnn, const float* __restrict__ phrnn,
                  const float* __restrict__ syl,
                  const float* __restrict__ Wx_f, const float* __restrict__ Wh_f,
                  const float* __restrict__ b_f,
                  const float* __restrict__ Wx_p, const float* __restrict__ Wh_p,
                  const float* __restrict__ b_p,
                  const float* __restrict__ Wx_s, const float* __restrict__ Wh_s,
                  const float* __restrict__ b_s,
                  const int* __restrict__ fclk, const int* __restrict__ pclk,
                  const int* __restrict__ sfreq,
                  float* __restrict__ out)
{
    __shared__ unsigned char sFlag[T_STEPS];
    __shared__ __align__(16) float sIn [DF  * 4];   // (xf0,xp0,xf1,xp1)[j<8]
    __shared__ __align__(16) float sHfp[HID * 4];   // (hf0,hp0,hf1,hp1)[j] (A recurrence)
    // Per-element B operand arrays, 8B/row: component .x published by A/loaders,
    // .y by B owners. LDS.128 covers 2 rows -> 4 FMA2 per load.
    __shared__ __align__(16) ull sR0[2 * EPAD];  // (hf, hs0)[j]
    __shared__ __align__(16) ull sR1[2 * EPAD];  // (hp, hs1)[j]
    __shared__ __align__(16) ull sR2[2 * EPAD];  // (xs, hs2)[j]  (.x stays 0 for j>=24!)

    const int lane = threadIdx.x;
    const int b0   = blockIdx.x * 2;

    // ---- prologue (single warp per CTA: syncwarp suffices) ----
    for (int t = lane; t < T_STEPS; t += 32) {
        unsigned f = 0u;
        if ((t % (fclk[t] + 1)) == 0) f |= 1u;
        if ((t % (pclk[t] + 1)) == 0) f |= 2u;
        if (sfreq[t] == 1)            f |= 4u;
        sFlag[t] = (unsigned char)f;
    }
    for (int i = lane; i < 2 * EPAD; i += 32) {
        sR0[i] = 0ull; sR1[i] = 0ull; sR2[i] = 0ull;  // incl. permanent xs zero-pad
    }
    *(float4*)&sHfp[lane * 4] = make_float4(0.f, 0.f, 0.f, 0.f);
    __syncwarp();

    // ---- register-resident weights ----
    ull wA[DF + HID];              // A: lane = neuron, (f,p) packed
    #pragma unroll
    for (int j = 0; j < DF; j++)
        wA[j] = f2_pack(Wx_f[j * HID + lane], Wx_p[j * HID + lane]);
    #pragma unroll
    for (int j = 0; j < HID; j++)
        wA[DF + j] = f2_pack(Wh_f[j * HID + lane], Wh_p[j * HID + lane]);

    const int eB = lane >> 4;      // B: element this lane serves
    const int nb = lane & 15;
    const int n0 = nb * 2, n1 = n0 + 1;   // B: 2 owned neurons
    ull wS0[HID], wS1[HID];        // (Wx_s, Wh_s) per owned neuron
    #pragma unroll
    for (int j = 0; j < HID; j++) {
        wS0[j] = f2_pack(Wx_s[j * HID + n0], Wh_s[j * HID + n0]);
        wS1[j] = f2_pack(Wx_s[j * HID + n1], Wh_s[j * HID + n1]);
    }
    const ull   biasfp = f2_pack(b_f[lane], b_p[lane]);
    const float bs0 = b_s[n0], bs1 = b_s[n1];

    // ---- loader roles (as R14) ----
    int eL = 0, chunk = 0;
    const float* baseP = 0;
    int strideT = 0;
    const bool loader = lane < 20;
    if (lane < 8) {
        eL = (lane >> 1) & 1;
        chunk = lane & 1;
        baseP = ((lane < 4) ? frnn : phrnn) + (b0 + eL) * DF + chunk * 4;
        strideT = BATCH * DF;
    } else if (lane < 20) {
        int r = lane - 8;
        eL = r / 6;
        chunk = r - 6 * eL;
        baseP = syl + (b0 + eL) * DS + chunk * 4;
        strideT = BATCH * DS;
    }
    const int compA = eL * 2 + ((lane >= 4 && lane < 8) ? 1 : 0);
    const int jb    = chunk * 4;

    // ---- register state ----
    float hf0 = 0.f, hp0 = 0.f, hf1 = 0.f, hp1 = 0.f;   // A: neuron=lane, elems 0,1
    float hs0a = 0.f, hs0b = 0.f;                        // B: elem eB, neurons n0,n1
    float hs1a = 0.f, hs1b = 0.f;
    float hs2a = 0.f, hs2b = 0.f;

    float4 cur = loader ? *(const float4*)baseP : make_float4(0.f, 0.f, 0.f, 0.f);
    unsigned fl = sFlag[0];

    for (int t = 0; t < T_STEPS; t++) {
        float4 nxt = make_float4(0.f, 0.f, 0.f, 0.f);
        if (loader && t + 1 < T_STEPS)
            nxt = *(const float4*)(baseP + (size_t)(t + 1) * strideT);
        const unsigned fl_n = (t + 1 < T_STEPS) ? (unsigned)sFlag[t + 1] : 0u;

        // ================= phase A: f & p cells (unchanged from R14) =============
        if (fl & 3u) {
            if (lane < 8) {
                sIn[(jb + 0) * 4 + compA] = cur.x;
                sIn[(jb + 1) * 4 + compA] = cur.y;
                sIn[(jb + 2) * 4 + compA] = cur.z;
                sIn[(jb + 3) * 4 + compA] = cur.w;
            }
            __syncwarp();

            ull a0A = biasfp, a0B = 0ull, a1A = biasfp, a1B = 0ull;
            #pragma unroll
            for (int j = 0; j < DF; j++) {
                ulonglong2 op = *(const ulonglong2*)&sIn[j * 4];
                if (j & 1) { a0B = f2_fma(op.x, wA[j], a0B); a1B = f2_fma(op.y, wA[j], a1B); }
                else       { a0A = f2_fma(op.x, wA[j], a0A); a1A = f2_fma(op.y, wA[j], a1A); }
            }
            #pragma unroll
            for (int j = 0; j < HID; j++) {
                ulonglong2 op = *(const ulonglong2*)&sHfp[j * 4];
                if (j & 1) { a0B = f2_fma(op.x, wA[DF + j], a0B); a1B = f2_fma(op.y, wA[DF + j], a1B); }
                else       { a0A = f2_fma(op.x, wA[DF + j], a0A); a1A = f2_fma(op.y, wA[DF + j], a1A); }
            }
            float af0, ap0, af1, ap1;
            f2_unpack(f2_add(a0A, a0B), af0, ap0);
            f2_unpack(f2_add(a1A, a1B), af1, ap1);
            if (fl & 1u) { hf0 = fast_tanh(af0); hf1 = fast_tanh(af1); }
            if (fl & 2u) { hp0 = fast_tanh(ap0); hp1 = fast_tanh(ap1); }
            __syncwarp();   // all lanes done reading old sHfp
            *(float4*)&sHfp[lane * 4] = make_float4(hf0, hp0, hf1, hp1);
        }

        // ================= phase B: syl cell, 2-neuron ownership =================
        if (fl & 4u) {
            __syncwarp();   // prior B matvec reads complete before overwrite
            // publish operands: .x from A-state (lane=neuron, both elems) + xs;
            //                   .y from B-state (elem eB, neurons n0,n1)
            ((float*)&sR0[0 * EPAD + lane])[0] = hf0;
            ((float*)&sR0[1 * EPAD + lane])[0] = hf1;
            ((float*)&sR1[0 * EPAD + lane])[0] = hp0;
            ((float*)&sR1[1 * EPAD + lane])[0] = hp1;
            ((float*)&sR0[eB * EPAD + n0])[1] = hs0a;
            ((float*)&sR0[eB * EPAD + n1])[1] = hs0b;
            ((float*)&sR1[eB * EPAD + n0])[1] = hs1a;
            ((float*)&sR1[eB * EPAD + n1])[1] = hs1b;
            ((float*)&sR2[eB * EPAD + n0])[1] = hs2a;
            ((float*)&sR2[eB * EPAD + n1])[1] = hs2b;
            if (lane >= 8 && lane < 20) {
                ((float*)&sR2[eL * EPAD + jb + 0])[0] = cur.x;
                ((float*)&sR2[eL * EPAD + jb + 1])[0] = cur.y;
                ((float*)&sR2[eL * EPAD + jb + 2])[0] = cur.z;
                ((float*)&sR2[eL * EPAD + jb + 3])[0] = cur.w;
            }
            __syncwarp();

            const ull* R0 = &sR0[eB * EPAD];
            const ull* R1 = &sR1[eB * EPAD];
            const ull* R2 = &sR2[eB * EPAD];
            // accumulators: (x-part, h-part) per row per owned neuron
            ull q00 = f2_pack(bs0, 0.f), q01 = q00, q02 = q00;
            ull q10 = f2_pack(bs1, 0.f), q11 = q10, q12 = q10;
            #pragma unroll
            for (int k = 0; k < HID / 2; k++) {
                ulonglong2 v0 = *(const ulonglong2*)&R0[2 * k];  // rows 2k,2k+1 of (hf,hs0)
                ulonglong2 v1 = *(const ulonglong2*)&R1[2 * k];
                ulonglong2 v2 = *(const ulonglong2*)&R2[2 * k];
                q00 = f2_fma(v0.x, wS0[2 * k], q00);
                q10 = f2_fma(v0.x, wS1[2 * k], q10);
                q01 = f2_fma(v1.x, wS0[2 * k], q01);
                q11 = f2_fma(v1.x, wS1[2 * k], q11);
                q02 = f2_fma(v2.x, wS0[2 * k], q02);
                q12 = f2_fma(v2.x, wS1[2 * k], q12);
                q00 = f2_fma(v0.y, wS0[2 * k + 1], q00);
                q10 = f2_fma(v0.y, wS1[2 * k + 1], q10);
                q01 = f2_fma(v1.y, wS0[2 * k + 1], q01);
                q11 = f2_fma(v1.y, wS1[2 * k + 1], q11);
                q02 = f2_fma(v2.y, wS0[2 * k + 1], q02);
                q12 = f2_fma(v2.y, wS1[2 * k + 1], q12);
            }
            float xa, ha;
            f2_unpack(q00, xa, ha); hs0a = fast_tanh(xa + ha);
            f2_unpack(q01, xa, ha); hs1a = fast_tanh(xa + ha);
            f2_unpack(q02, xa, ha); hs2a = fast_tanh(xa + ha);
            f2_unpack(q10, xa, ha); hs0b = fast_tanh(xa + ha);
            f2_unpack(q11, xa, ha); hs1b = fast_tanh(xa + ha);
            f2_unpack(q12, xa, ha); hs2b = fast_tanh(xa + ha);
        }

        cur = nxt;
        fl  = fl_n;
    }

    // output h_s: [3, B, H]; lane owns (elem eB, neurons n0,n1)
    const int bidx = b0 + eB;
    *(float2*)&out[(0 * BATCH + bidx) * HID + n0] = make_float2(hs0a, hs0b);
    *(float2*)&out[(1 * BATCH + bidx) * HID + n0] = make_float2(hs1a, hs1b);
    *(float2*)&out[(2 * BATCH + bidx) * HID + n0] = make_float2(hs2a, hs2b);
}

extern "C" void kernel_launch(void* const* d_in, const int* in_sizes, int n_in,
                              void* d_out, int out_size) {
    const float* frnn  = (const float*)d_in[0];
    const float* phrnn = (const float*)d_in[1];
    const float* syl   = (const float*)d_in[2];
    const float* Wx_f  = (const float*)d_in[3];
    const float* Wh_f  = (const float*)d_in[4];
    const float* b_f   = (const float*)d_in[5];
    const float* Wx_p  = (const float*)d_in[6];
    const float* Wh_p  = (const float*)d_in[7];
    const float* b_p   = (const float*)d_in[8];
    const float* Wx_s  = (const float*)d_in[9];
    const float* Wh_s  = (const float*)d_in[10];
    const float* b_s   = (const float*)d_in[11];
    const int*   fclk  = (const int*)d_in[12];
    const int*   pclk  = (const int*)d_in[13];
    const int*   sfreq = (const int*)d_in[14];
    float* out = (float*)d_out;

    dim3 grid(BATCH / 2);   // 1 warp/CTA, 2 elements
    dim3 block(32);
    chive_kernel<<<grid, block>>>(frnn, phrnn, syl,
                                  Wx_f, Wh_f, b_f,
                                  Wx_p, Wh_p, b_p,
                                  Wx_s, Wh_s, b_s,
                                  fclk, pclk, sfreq, out);
}

// round 16
// speedup vs baseline: 1.2870x; 1.2870x over previous
#include <cuda_runtime.h>

#define T_STEPS 2048
#define BATCH   2048
#define HID     32
#define DF      8
#define DS      24
#define NWARP   8     // 8 warps/CTA -> warps on all 4 SMSPs (wid%4)

typedef unsigned long long ull;

// ---------- f32x2 packed helpers (sm_100+) ----------
__device__ __forceinline__ ull f2_fma(ull a, ull b, ull c) {
    ull d;
    asm("fma.rn.f32x2 %0, %1, %2, %3;" : "=l"(d) : "l"(a), "l"(b), "l"(c));
    return d;
}
__device__ __forceinline__ ull f2_add(ull a, ull b) {
    ull d;
    asm("add.rn.f32x2 %0, %1, %2;" : "=l"(d) : "l"(a), "l"(b));
    return d;
}
__device__ __forceinline__ ull f2_pack(float lo, float hi) {
    ull d;
    asm("mov.b64 %0, {%1, %2};" : "=l"(d) : "f"(lo), "f"(hi));
    return d;
}
__device__ __forceinline__ void f2_unpack(ull v, float &lo, float &hi) {
    asm("mov.b64 {%0, %1}, %2;" : "=f"(lo), "=f"(hi) : "l"(v));
}

// tanh(x) = sign(x) * (1 - e) / (1 + e), e = exp(-2|x|). ~1e-6 abs error.
__device__ __forceinline__ float fast_tanh(float x) {
    float ax = fabsf(x);
    float e  = __expf(-2.0f * ax);
    float r  = __fdividef(1.0f - e, 1.0f + e);
    return __int_as_float((__float_as_int(x) & 0x80000000) | __float_as_int(r));
}

__global__ __launch_bounds__(NWARP * 32)
void chive_kernel(const float* __restrict__ frnn, const float* __restrict__ phrnn,
                  const float* __restrict__ syl,
                  const float* __restrict__ Wx_f, const float* __restrict__ Wh_f,
                  const float* __restrict__ b_f,
                  const float* __restrict__ Wx_p, const float* __restrict__ Wh_p,
                  const float* __restrict__ b_p,
                  const float* __restrict__ Wx_s, const float* __restrict__ Wh_s,
                  const float* __restrict__ b_s,
                  const int* __restrict__ fclk, const int* __restrict__ pclk,
                  const int* __restrict__ sfreq,
                  float* __restrict__ out)
{
    __shared__ unsigned char sFlag[T_STEPS];
    // Per-warp broadcast arrays (float4-granular; read as ulonglong2 broadcasts)
    __shared__ __align__(16) float sIn [NWARP][DF  * 4]; // (xf0,xp0,xf1,xp1)[j<8]
    __shared__ __align__(16) float sHfp[NWARP][HID * 4]; // (hf0,hp0,hf1,hp1)[j]
    __shared__ __align__(16) float sQa [NWARP][HID * 4]; // (hf0,hs0_0,hp0,hs1_0)[j]
    __shared__ __align__(16) float sQb [NWARP][HID * 4]; // (hf1,hs0_1,hp1,hs1_1)[j]
    __shared__ __align__(16) float sQ2 [NWARP][HID * 4]; // (xs0,hs2_0,xs1,hs2_1)[j]

    const int tid  = threadIdx.x;
    const int w    = tid >> 5;
    const int lane = tid & 31;
    const int b0   = (blockIdx.x * NWARP + w) * 2;   // 2 elements per warp

    // ---- prologue: flags + zero-init of state arrays ----
    for (int t = tid; t < T_STEPS; t += NWARP * 32) {
        unsigned f = 0u;
        if ((t % (fclk[t] + 1)) == 0) f |= 1u;
        if ((t % (pclk[t] + 1)) == 0) f |= 2u;
        if (sfreq[t] == 1)            f |= 4u;
        sFlag[t] = (unsigned char)f;
    }
    // zero: h0 = 0 AND the permanent x_s zero-pad in sQ2 (.x/.z for j>=24 are
    // never written again -- must stay 0; learned the hard way in R9).
    *(float4*)&sHfp[w][lane * 4] = make_float4(0.f, 0.f, 0.f, 0.f);
    *(float4*)&sQ2 [w][lane * 4] = make_float4(0.f, 0.f, 0.f, 0.f);
    __syncthreads();

    // ---- register-resident weights: lane = output neuron ----
    ull wA[DF + HID];   // (Wx_f,Wx_p) rows then (Wh_f,Wh_p) rows
    ull wS[HID];        // (Wx_s, Wh_s) rows
    #pragma unroll
    for (int j = 0; j < DF; j++)
        wA[j] = f2_pack(Wx_f[j * HID + lane], Wx_p[j * HID + lane]);
    #pragma unroll
    for (int j = 0; j < HID; j++) {
        wA[DF + j] = f2_pack(Wh_f[j * HID + lane], Wh_p[j * HID + lane]);
        wS[j]      = f2_pack(Wx_s[j * HID + lane], Wh_s[j * HID + lane]);
    }
    const ull   biasfp = f2_pack(b_f[lane], b_p[lane]);
    const float bsl    = b_s[lane];

    float* In_  = sIn[w];
    float* Hfp_ = sHfp[w];
    float* Qa_  = sQa[w];
    float* Qb_  = sQb[w];
    float* Q2_  = sQ2[w];

    // ---- loader roles (identical to R14) ----
    int e = 0, chunk = 0;
    const float* baseP = 0;
    int strideT = 0;
    const bool loader = lane < 20;
    if (lane < 8) {
        e = (lane >> 1) & 1;
        chunk = lane & 1;
        baseP = ((lane < 4) ? frnn : phrnn) + (b0 + e) * DF + chunk * 4;
        strideT = BATCH * DF;
    } else if (lane < 20) {
        int r = lane - 8;
        e = r / 6;
        chunk = r - 6 * e;
        baseP = syl + (b0 + e) * DS + chunk * 4;
        strideT = BATCH * DS;
    }
    const int compA = e * 2 + ((lane >= 4 && lane < 8) ? 1 : 0);
    const int compS = e * 2;
    const int jb    = chunk * 4;

    // register state (this lane's neuron, both elements)
    float hf0 = 0.f, hp0 = 0.f, hs0_0 = 0.f, hs1_0 = 0.f, hs2_0 = 0.f;
    float hf1 = 0.f, hp1 = 0.f, hs0_1 = 0.f, hs1_1 = 0.f, hs2_1 = 0.f;

    float4 cur = loader ? *(const float4*)baseP : make_float4(0.f, 0.f, 0.f, 0.f);
    unsigned fl = sFlag[0];

    for (int t = 0; t < T_STEPS; t++) {
        float4 nxt = make_float4(0.f, 0.f, 0.f, 0.f);
        if (loader && t + 1 < T_STEPS)
            nxt = *(const float4*)(baseP + (size_t)(t + 1) * strideT);
        const unsigned fl_n = (t + 1 < T_STEPS) ? (unsigned)sFlag[t + 1] : 0u;

        // ================= phase A: f & p cells =================
        if (fl & 3u) {
            if (lane < 8) {
                In_[(jb + 0) * 4 + compA] = cur.x;
                In_[(jb + 1) * 4 + compA] = cur.y;
                In_[(jb + 2) * 4 + compA] = cur.z;
                In_[(jb + 3) * 4 + compA] = cur.w;
            }
            __syncwarp();

            ull a0A = biasfp, a0B = 0ull, a1A = biasfp, a1B = 0ull;
            #pragma unroll
            for (int j = 0; j < DF; j++) {
                ulonglong2 op = *(const ulonglong2*)&In_[j * 4]; // (xf0,xp0)(xf1,xp1)
                if (j & 1) { a0B = f2_fma(op.x, wA[j], a0B); a1B = f2_fma(op.y, wA[j], a1B); }
                else       { a0A = f2_fma(op.x, wA[j], a0A); a1A = f2_fma(op.y, wA[j], a1A); }
            }
            #pragma unroll
            for (int j = 0; j < HID; j++) {
                ulonglong2 op = *(const ulonglong2*)&Hfp_[j * 4]; // (hf0,hp0)(hf1,hp1)
                if (j & 1) { a0B = f2_fma(op.x, wA[DF + j], a0B); a1B = f2_fma(op.y, wA[DF + j], a1B); }
                else       { a0A = f2_fma(op.x, wA[DF + j], a0A); a1A = f2_fma(op.y, wA[DF + j], a1A); }
            }
            float af0, ap0, af1, ap1;
            f2_unpack(f2_add(a0A, a0B), af0, ap0);
            f2_unpack(f2_add(a1A, a1B), af1, ap1);
            if (fl & 1u) { hf0 = fast_tanh(af0); hf1 = fast_tanh(af1); }
            if (fl & 2u) { hp0 = fast_tanh(ap0); hp1 = fast_tanh(ap1); }
            __syncwarp();   // all lanes done reading old Hfp_
            *(float4*)&Hfp_[lane * 4] = make_float4(hf0, hp0, hf1, hp1);
        }

        // ================= phase B: syl cell (3 rows x 2 elems) =================
        if (fl & 4u) {
            __syncwarp();   // all lanes past previous B reads (also covers Hfp publish)
            *(float4*)&Qa_[lane * 4] = make_float4(hf0, hs0_0, hp0, hs1_0);
            *(float4*)&Qb_[lane * 4] = make_float4(hf1, hs0_1, hp1, hs1_1);
            Q2_[lane * 4 + 1] = hs2_0;
            Q2_[lane * 4 + 3] = hs2_1;
            if (lane >= 8 && lane < 20) {
                Q2_[(jb + 0) * 4 + compS] = cur.x;
                Q2_[(jb + 1) * 4 + compS] = cur.y;
                Q2_[(jb + 2) * 4 + compS] = cur.z;
                Q2_[(jb + 3) * 4 + compS] = cur.w;
            }
            __syncwarp();

            // accumulators: (x-stack part, Wh part) per row per element
            ull r00 = f2_pack(bsl, 0.f);
            ull r10 = r00, r20 = r00, r01 = r00, r11 = r00, r21 = r00;
            #pragma unroll
            for (int j = 0; j < HID; j++) {
                ull wv = wS[j];                                   // (Wx_s, Wh_s)
                ulonglong2 qa = *(const ulonglong2*)&Qa_[j * 4];  // (hf0,hs0_0)(hp0,hs1_0)
                ulonglong2 qb = *(const ulonglong2*)&Qb_[j * 4];
                ulonglong2 q2 = *(const ulonglong2*)&Q2_[j * 4];  // (xs0,hs2_0)(xs1,hs2_1)
                r00 = f2_fma(qa.x, wv, r00);
                r10 = f2_fma(qa.y, wv, r10);
                r01 = f2_fma(qb.x, wv, r01);
                r11 = f2_fma(qb.y, wv, r11);
                r20 = f2_fma(q2.x, wv, r20);
                r21 = f2_fma(q2.y, wv, r21);
            }
            float xa, ha;
            f2_unpack(r00, xa, ha); hs0_0 = fast_tanh(xa + ha);
            f2_unpack(r10, xa, ha); hs1_0 = fast_tanh(xa + ha);
            f2_unpack(r20, xa, ha); hs2_0 = fast_tanh(xa + ha);
            f2_unpack(r01, xa, ha); hs0_1 = fast_tanh(xa + ha);
            f2_unpack(r11, xa, ha); hs1_1 = fast_tanh(xa + ha);
            f2_unpack(r21, xa, ha); hs2_1 = fast_tanh(xa + ha);
        }

        cur = nxt;
        fl  = fl_n;
    }

    // output h_s: [3, B, H]
    out[(0 * BATCH + b0    ) * HID + lane] = hs0_0;
    out[(1 * BATCH + b0    ) * HID + lane] = hs1_0;
    out[(2 * BATCH + b0    ) * HID + lane] = hs2_0;
    out[(0 * BATCH + b0 + 1) * HID + lane] = hs0_1;
    out[(1 * BATCH + b0 + 1) * HID + lane] = hs1_1;
    out[(2 * BATCH + b0 + 1) * HID + lane] = hs2_1;
}

extern "C" void kernel_launch(void* const* d_in, const int* in_sizes, int n_in,
                              void* d_out, int out_size) {
    const float* frnn  = (const float*)d_in[0];
    const float* phrnn = (const float*)d_in[1];
    const float* syl   = (const float*)d_in[2];
    const float* Wx_f  = (const float*)d_in[3];
    const float* Wh_f  = (const float*)d_in[4];
    const float* b_f   = (const float*)d_in[5];
    const float* Wx_p  = (const float*)d_in[6];
    const float* Wh_p  = (const float*)d_in[7];
    const float* b_p   = (const float*)d_in[8];
    const float* Wx_s  = (const float*)d_in[9];
    const float* Wh_s  = (const float*)d_in[10];
    const float* b_s   = (const float*)d_in[11];
    const int*   fclk  = (const int*)d_in[12];
    const int*   pclk  = (const int*)d_in[13];
    const int*   sfreq = (const int*)d_in[14];
    float* out = (float*)d_out;

    dim3 grid(BATCH / (NWARP * 2));   // 128 CTAs: one per SM, all 4 SMSPs fed
    dim3 block(NWARP * 32);
    chive_kernel<<<grid, block>>>(frnn, phrnn, syl,
                                  Wx_f, Wh_f, b_f,
                                  Wx_p, Wh_p, b_p,
                                  Wx_s, Wh_s, b_s,
                                  fclk, pclk, sfreq, out);
}